// round 5
// baseline (speedup 1.0000x reference)
#include <cuda_runtime.h>
#include <cuda_bf16.h>
#include <cstdint>

// Problem constants (fixed shapes for TimeWindowBlock_3925600108827)
#define H   64      // hidden
#define FF  36      // MLP hidden
#define SEQ 200     // S
#define NW  8       // W windows
#define KPAD (H + 4)   // padded smem row stride (68 floats, conflict-free)

typedef unsigned long long u64;

// -------- mask dtype autodetection (bool may arrive as i32 / f32 / u8) ----
__device__ int g_mask_mode;   // 0 = int32, 1 = float32, 2 = byte

__global__ void detect_mask_kernel(const unsigned int* m, int nwords) {
    __shared__ int s_not01, s_not0f;
    if (threadIdx.x == 0) { s_not01 = 0; s_not0f = 0; }
    __syncthreads();
    int n01 = 0, n0f = 0;
    for (int i = threadIdx.x; i < nwords; i += blockDim.x) {
        unsigned int w = m[i];
        if (w > 1u) n01 = 1;
        if (w != 0u && w != 0x3f800000u) n0f = 1;
    }
    if (n01) s_not01 = 1;
    if (n0f) s_not0f = 1;
    __syncthreads();
    if (threadIdx.x == 0)
        g_mask_mode = (!s_not01) ? 0 : ((!s_not0f) ? 1 : 2);
}

// -------- packed fp32x2 helpers (sm_100+ PTX) ------------------------------
__device__ __forceinline__ u64 ffma2(u64 a, u64 b, u64 c) {
    u64 d;
    asm("fma.rn.f32x2 %0, %1, %2, %3;" : "=l"(d) : "l"(a), "l"(b), "l"(c));
    return d;
}
__device__ __forceinline__ float2 up2(u64 v) {
    float2 r;
    asm("mov.b64 {%0, %1}, %2;" : "=f"(r.x), "=f"(r.y) : "l"(v));
    return r;
}

__device__ __forceinline__ float wredmax(float v) {
    #pragma unroll
    for (int o = 16; o; o >>= 1) v = fmaxf(v, __shfl_xor_sync(0xffffffffu, v, o));
    return v;
}
__device__ __forceinline__ float wredsum(float v) {
    #pragma unroll
    for (int o = 16; o; o >>= 1) v += __shfl_xor_sync(0xffffffffu, v, o);
    return v;
}

// Dynamic smem layout (floats):
//  sK      : SEQ*KPAD          = 13600
//  sM      : FF*H              = 2304
//  sC      : FF                = 36
//  sW2     : FF                = 36
//  sQ      : H                 = 64
//  sScore  : SEQ               = 200
//  sRed    : 256               = 256
// total = 16496 floats = 65,984 bytes
#define SMEM_FLOATS (SEQ*KPAD + FF*H + FF + FF + H + SEQ + 256)

__global__ void __launch_bounds__(256, 2)
twb_kernel(const float* __restrict__ query,
           const float* __restrict__ key,
           const float* __restrict__ W1,
           const float* __restrict__ b1,
           const float* __restrict__ prelu_a,
           const float* __restrict__ W2,
           const float* __restrict__ b2,
           const void*  __restrict__ maskp,
           float* __restrict__ out)
{
    extern __shared__ float smem[];
    float* sK     = smem;                 // [SEQ][KPAD]
    float* sM     = sK + SEQ * KPAD;      // [FF][H]
    float* sC     = sM + FF * H;          // [FF]
    float* sW2    = sC + FF;              // [FF]
    float* sQ     = sW2 + FF;             // [H]
    float* sScore = sQ + H;               // [SEQ]
    float* sRed   = sScore + SEQ;         // [256]

    const int cta = blockIdx.x;           // b*NW + w
    const int b   = cta >> 3;             // NW == 8
    const int tid = threadIdx.x;
    const int lane = tid & 31;
    const int wid5 = tid >> 5;

    // ---- Phase 1: load q row + k tile into smem -------------------------
    if (tid < H) sQ[tid] = query[b * H + tid];

    const float4* kg = reinterpret_cast<const float4*>(key + (size_t)cta * SEQ * H);
    float4* sK4 = reinterpret_cast<float4*>(sK);
    #pragma unroll 4
    for (int i = tid; i < SEQ * (H / 4); i += 256) {
        int s  = i >> 4;          // H/4 == 16 float4 per row
        int c4 = i & 15;
        sK4[s * (KPAD / 4) + c4] = kg[i];    // KPAD/4 == 17
    }
    __syncthreads();

    // ---- Phase 2: build per-batch folded matrix M_b, bias c_b, W2 copy --
    // M[o][d] = W1[o,64+d] - W1[o,128+d] + W1[o,192+d] * q[d]
    for (int i = tid; i < FF * H; i += 256) {
        int o = i >> 6, d = i & 63;
        const float* w1r = W1 + o * 256;
        sM[i] = w1r[64 + d] - w1r[128 + d] + w1r[192 + d] * sQ[d];
    }
    // c[o] = b1[o] + sum_d (W1[o,d] + W1[o,128+d]) * q[d]
    if (tid < FF) {
        const float* w1r = W1 + tid * 256;
        float acc = b1[tid];
        #pragma unroll 8
        for (int d = 0; d < H; d++)
            acc = fmaf(w1r[d] + w1r[128 + d], sQ[d], acc);
        sC[tid]  = acc;
        sW2[tid] = W2[tid];
    }
    __syncthreads();

    // ---- Phase 3: per-s score = W2 . PReLU(M k_s + c) + b2 --------------
    const float pa  = prelu_a[0];
    const float b2v = b2[0];
    float score = -1e30f;

    if (tid < SEQ) {
        // k row -> 32 packed f32x2 registers
        const ulonglong2* krow =
            reinterpret_cast<const ulonglong2*>(sK + tid * KPAD);
        u64 kk[32];
        #pragma unroll
        for (int j = 0; j < 16; j++) {
            ulonglong2 t = krow[j];
            kk[2 * j]     = t.x;
            kk[2 * j + 1] = t.y;
        }

        float sc = b2v;
        #pragma unroll 2
        for (int o = 0; o < FF; o++) {
            const ulonglong2* mrow =
                reinterpret_cast<const ulonglong2*>(sM + o * H);
            u64 a0 = 0ull, a1 = 0ull;      // bits of (0.f, 0.f)
            #pragma unroll
            for (int j = 0; j < 16; j++) {
                ulonglong2 m = mrow[j];    // broadcast LDS.128
                a0 = ffma2(m.x, kk[2 * j],     a0);
                a1 = ffma2(m.y, kk[2 * j + 1], a1);
            }
            float2 f0 = up2(a0), f1 = up2(a1);
            float h = (f0.x + f0.y) + (f1.x + f1.y) + sC[o];
            h = (h >= 0.f) ? h : pa * h;          // PReLU
            sc = fmaf(sW2[o], h, sc);
        }

        // mask: True -> -10000 (before softmax)
        size_t midx = (size_t)cta * SEQ + tid;
        int mode = g_mask_mode;
        bool masked;
        if (mode == 0)      masked = ((const int*)maskp)[midx] != 0;
        else if (mode == 1) masked = ((const float*)maskp)[midx] != 0.0f;
        else                masked = ((const unsigned char*)maskp)[midx] != 0;
        score = masked ? -10000.0f : sc;
    }

    // ---- Phase 4: softmax over SEQ ---------------------------------------
    float wm = wredmax(score);
    if (lane == 0) sRed[wid5] = wm;
    __syncthreads();
    float mx = sRed[0];
    #pragma unroll
    for (int i = 1; i < 8; i++) mx = fmaxf(mx, sRed[i]);
    __syncthreads();                       // before reusing sRed

    float e = (tid < SEQ) ? __expf(score - mx) : 0.0f;
    if (tid < SEQ) sScore[tid] = e;
    float ws = wredsum(e);
    if (lane == 0) sRed[wid5] = ws;
    __syncthreads();
    float sum = sRed[0];
    #pragma unroll
    for (int i = 1; i < 8; i++) sum += sRed[i];
    float inv = 1.0f / sum;

    // ---- Phase 5: out[d] = inv * sum_s e_s * k[s][d] ---------------------
    int d = tid & 63, g = tid >> 6;        // 4 groups x 64 dims
    float acc = 0.0f;
    #pragma unroll 5
    for (int s = g; s < SEQ; s += 4)
        acc = fmaf(sScore[s], sK[s * KPAD + d], acc);

    __syncthreads();                       // all sRed reads done
    sRed[tid] = acc;
    __syncthreads();
    if (tid < 64) {
        float r = (sRed[tid] + sRed[tid + 64] + sRed[tid + 128] + sRed[tid + 192]) * inv;
        out[(size_t)cta * H + tid] = r;
    }
}

extern "C" void kernel_launch(void* const* d_in, const int* in_sizes, int n_in,
                              void* d_out, int out_size) {
    const float* query = (const float*)d_in[0];
    const float* key   = (const float*)d_in[1];
    const float* W1    = (const float*)d_in[2];
    const float* b1    = (const float*)d_in[3];
    const float* pa    = (const float*)d_in[4];
    const float* W2    = (const float*)d_in[5];
    const float* b2    = (const float*)d_in[6];
    const void*  mask  = d_in[7];
    float* out = (float*)d_out;

    int n_bw = in_sizes[1] / (SEQ * H);    // B*W (= 4096)

    // mask dtype detection: safe to scan 4096 words for any candidate layout
    detect_mask_kernel<<<1, 256>>>((const unsigned int*)mask, 4096);

    const int smem_bytes = SMEM_FLOATS * (int)sizeof(float);
    cudaFuncSetAttribute(twb_kernel,
                         cudaFuncAttributeMaxDynamicSharedMemorySize,
                         smem_bytes);
    twb_kernel<<<n_bw, 256, smem_bytes>>>(query, key, W1, b1, pa, W2, b2,
                                          mask, out);
}